// round 1
// baseline (speedup 1.0000x reference)
#include <cuda_runtime.h>
#include <cstdint>
#include <mma.h>
using namespace nvcuda;

#define NTOK 4096
#define DDIM 1024
#define EEXP 8
#define HDIM 4096

#define BM 128
#define BN 128
#define BK 32
#define LDA 40
#define LDB 136
#define ASTAGE (BM*LDA)          // 5120 floats
#define BSTAGE (BK*LDB)          // 4352 floats
#define SMEM_FLOATS (2*ASTAGE + 2*BSTAGE)   // 18944
#define SMEM_BYTES (SMEM_FLOATS*4)          // 75776
#define LDC 132

// Scratch (device globals: no runtime allocation allowed)
__device__ float g_h[(size_t)NTOK*2*HDIM];   // 8192 x 4096 fp32 = 128MB
__device__ int   g_counts[EEXP];
__device__ int   g_offsets[EEXP];
__device__ int   g_tok[EEXP*NTOK];
__device__ float g_wt[EEXP*NTOK];

__device__ __forceinline__ void cpa16(float* dst, const float* src){
    uint32_t d = (uint32_t)__cvta_generic_to_shared(dst);
    asm volatile("cp.async.cg.shared.global [%0], [%1], 16;\n" :: "r"(d), "l"(src));
}
__device__ __forceinline__ void cp_commit(){ asm volatile("cp.async.commit_group;\n"); }
template<int N> __device__ __forceinline__ void cp_wait(){
    asm volatile("cp.async.wait_group %0;\n" :: "n"(N));
}

__device__ __forceinline__ float gelu_tanh(float v){
    const float c = 0.7978845608028654f;
    float t = tanhf(c*(v + 0.044715f*v*v*v));
    return 0.5f*v*(1.0f+t);
}

__global__ void init_kernel(){
    int t = threadIdx.x;
    if (t < EEXP) g_counts[t] = 0;
}

// One warp per token: logits = x[n] @ Wg + bg; top-2 + softmax; build expert lists.
__global__ void router_kernel(const float* __restrict__ x, const float* __restrict__ Wg,
                              const float* __restrict__ bg, float* __restrict__ logits_out,
                              int write_logits){
    int warp = threadIdx.x >> 5;
    int lane = threadIdx.x & 31;
    int n = blockIdx.x * 8 + warp;
    if (n >= NTOK) return;
    const float* xr = x + (size_t)n * DDIM;
    float l[EEXP];
    #pragma unroll
    for (int e = 0; e < EEXP; e++) l[e] = 0.f;
    for (int d = lane; d < DDIM; d += 32){
        float xv = xr[d];
        const float4* wp = (const float4*)(Wg + (size_t)d*EEXP);
        float4 wa = wp[0], wb = wp[1];
        l[0] += xv*wa.x; l[1] += xv*wa.y; l[2] += xv*wa.z; l[3] += xv*wa.w;
        l[4] += xv*wb.x; l[5] += xv*wb.y; l[6] += xv*wb.z; l[7] += xv*wb.w;
    }
    #pragma unroll
    for (int off = 16; off > 0; off >>= 1){
        #pragma unroll
        for (int e = 0; e < EEXP; e++)
            l[e] += __shfl_xor_sync(0xffffffff, l[e], off);
    }
    if (lane == 0){
        #pragma unroll
        for (int e = 0; e < EEXP; e++) l[e] += bg[e];
        if (write_logits){
            #pragma unroll
            for (int e = 0; e < EEXP; e++) logits_out[(size_t)n*EEXP + e] = l[e];
        }
        int e0 = 0;
        #pragma unroll
        for (int e = 1; e < EEXP; e++) if (l[e] > l[e0]) e0 = e;
        int e1 = (e0 == 0) ? 1 : 0;
        #pragma unroll
        for (int e = 0; e < EEXP; e++) if (e != e0 && l[e] > l[e1]) e1 = e;
        float a = l[e0], b = l[e1];
        float ex = expf(b - a);
        float s  = 1.0f / (1.0f + ex);
        float w0 = s, w1 = ex * s;
        int p0 = atomicAdd(&g_counts[e0], 1);
        g_tok[e0*NTOK + p0] = n; g_wt[e0*NTOK + p0] = w0;
        int p1 = atomicAdd(&g_counts[e1], 1);
        g_tok[e1*NTOK + p1] = n; g_wt[e1*NTOK + p1] = w1;
    }
}

__global__ void offsets_kernel(){
    if (threadIdx.x == 0){
        int s = 0;
        #pragma unroll
        for (int e = 0; e < EEXP; e++){ g_offsets[e] = s; s += g_counts[e]; }
    }
}

// MODE 1: h = gelu(gather(x) @ w1[e] + b1[e])   (A gathered by token list)
// MODE 2: out[tok] += wt * (h @ w2[e] + b2[e])  (A dense from g_h, atomic scatter)
template<int MODE>
__global__ void moe_gemm(const float* __restrict__ x, const float* __restrict__ W,
                         const float* __restrict__ bias, float* __restrict__ out){
    constexpr int Kdim = (MODE == 1) ? DDIM : HDIM;
    constexpr int Ndim = (MODE == 1) ? HDIM : DDIM;
    const int e = blockIdx.z;
    const int count = g_counts[e];
    const int mBase = blockIdx.y * BM;
    if (mBase >= count) return;
    const int off = g_offsets[e];
    const int n0 = blockIdx.x * BN;
    const int tid = threadIdx.x;

    extern __shared__ float smem[];
    float* Abuf0 = smem;
    float* Abuf1 = smem + ASTAGE;
    float* Bbuf0 = smem + 2*ASTAGE;
    float* Bbuf1 = smem + 2*ASTAGE + BSTAGE;

    // Per-thread A load slots (4 x 16B): row = idx/8, chunk = idx%8
    const float* aptr[4];
    int adoff[4];
    #pragma unroll
    for (int wv = 0; wv < 4; wv++){
        int idx = tid + wv*256;
        int row = idx >> 3, ch = idx & 7;
        int gr = mBase + row; if (gr > count-1) gr = count-1;
        if (MODE == 1){
            int tok = g_tok[e*NTOK + gr];
            aptr[wv] = x + (size_t)tok*DDIM + ch*4;
        } else {
            aptr[wv] = g_h + (size_t)(off+gr)*HDIM + ch*4;
        }
        adoff[wv] = row*LDA + ch*4;
    }
    // Per-thread B load slots: row = idx/32, chunk = idx%32
    const float* bptr[4];
    int bdoff[4];
    const float* Wb = W + (size_t)e*Kdim*Ndim + n0;
    #pragma unroll
    for (int wv = 0; wv < 4; wv++){
        int idx = tid + wv*256;
        int row = idx >> 5, ch = idx & 31;
        bptr[wv] = Wb + (size_t)row*Ndim + ch*4;
        bdoff[wv] = row*LDB + ch*4;
    }

    constexpr int KSTEPS = Kdim / BK;
    // prologue: stage 0
    #pragma unroll
    for (int wv = 0; wv < 4; wv++) cpa16(Abuf0 + adoff[wv], aptr[wv]);
    #pragma unroll
    for (int wv = 0; wv < 4; wv++) cpa16(Bbuf0 + bdoff[wv], bptr[wv]);
    cp_commit();

    const int warpId = tid >> 5;
    const int wr = warpId & 3;   // 4 warp-rows x 32
    const int wc = warpId >> 2;  // 2 warp-cols x 64

    using FragA = wmma::fragment<wmma::matrix_a, 16,16,8, wmma::precision::tf32, wmma::row_major>;
    using FragB = wmma::fragment<wmma::matrix_b, 16,16,8, wmma::precision::tf32, wmma::row_major>;
    using FragC = wmma::fragment<wmma::accumulator, 16,16,8, float>;
    FragC acc[2][4];
    #pragma unroll
    for (int i = 0; i < 2; i++)
        #pragma unroll
        for (int j = 0; j < 4; j++) wmma::fill_fragment(acc[i][j], 0.0f);

    #pragma unroll 1
    for (int kt = 0; kt < KSTEPS; kt++){
        int cur = kt & 1;
        if (kt + 1 < KSTEPS){
            float* An = (cur ? Abuf0 : Abuf1);
            float* Bn = (cur ? Bbuf0 : Bbuf1);
            size_t ka = (size_t)(kt+1) * BK;
            #pragma unroll
            for (int wv = 0; wv < 4; wv++) cpa16(An + adoff[wv], aptr[wv] + ka);
            #pragma unroll
            for (int wv = 0; wv < 4; wv++) cpa16(Bn + bdoff[wv], bptr[wv] + ka*Ndim);
            cp_commit();
            cp_wait<1>();
        } else {
            cp_wait<0>();
        }
        __syncthreads();
        float* As = (cur ? Abuf1 : Abuf0);
        float* Bs = (cur ? Bbuf1 : Bbuf0);
        #pragma unroll
        for (int kk = 0; kk < BK; kk += 8){
            FragA a[2];
            #pragma unroll
            for (int i = 0; i < 2; i++){
                wmma::load_matrix_sync(a[i], As + (wr*32 + i*16)*LDA + kk, LDA);
                #pragma unroll
                for (int t = 0; t < a[i].num_elements; t++)
                    a[i].x[t] = wmma::__float_to_tf32(a[i].x[t]);
            }
            #pragma unroll
            for (int j = 0; j < 4; j++){
                FragB b;
                wmma::load_matrix_sync(b, Bs + kk*LDB + wc*64 + j*16, LDB);
                #pragma unroll
                for (int t = 0; t < b.num_elements; t++)
                    b.x[t] = wmma::__float_to_tf32(b.x[t]);
                #pragma unroll
                for (int i = 0; i < 2; i++)
                    wmma::mma_sync(acc[i][j], a[i], b, acc[i][j]);
            }
        }
        __syncthreads();
    }

    // Epilogue: stage C tile in smem (reuse pipeline buffers), then masked writes.
    float* Cs = smem;   // needs 128*132 = 16896 floats <= 18944
    #pragma unroll
    for (int i = 0; i < 2; i++)
        #pragma unroll
        for (int j = 0; j < 4; j++)
            wmma::store_matrix_sync(Cs + (wr*32 + i*16)*LDC + wc*64 + j*16,
                                    acc[i][j], LDC, wmma::mem_row_major);
    __syncthreads();

    const float* be = bias + (size_t)e*Ndim + n0;
    #pragma unroll 1
    for (int it = 0; it < 16; it++){
        int idx4 = tid + it*256;
        int row = idx4 >> 5;
        int c4  = (idx4 & 31) * 4;
        int gr = mBase + row;
        if (gr < count){
            float4 v  = *(const float4*)(Cs + row*LDC + c4);
            float4 bb = *(const float4*)(be + c4);
            if (MODE == 1){
                float4 o;
                o.x = gelu_tanh(v.x + bb.x);
                o.y = gelu_tanh(v.y + bb.y);
                o.z = gelu_tanh(v.z + bb.z);
                o.w = gelu_tanh(v.w + bb.w);
                *(float4*)(g_h + (size_t)(off+gr)*HDIM + n0 + c4) = o;
            } else {
                int tok = g_tok[e*NTOK + gr];
                float wgt = g_wt[e*NTOK + gr];
                float* op = out + (size_t)tok*DDIM + n0 + c4;
                atomicAdd(op + 0, wgt*(v.x + bb.x));
                atomicAdd(op + 1, wgt*(v.y + bb.y));
                atomicAdd(op + 2, wgt*(v.z + bb.z));
                atomicAdd(op + 3, wgt*(v.w + bb.w));
            }
        }
    }
}

extern "C" void kernel_launch(void* const* d_in, const int* in_sizes, int n_in,
                              void* d_out, int out_size){
    const float* x  = (const float*)d_in[0];
    const float* Wg = (const float*)d_in[1];
    const float* bg = (const float*)d_in[2];
    const float* w1 = (const float*)d_in[3];
    const float* b1 = (const float*)d_in[4];
    const float* w2 = (const float*)d_in[5];
    const float* b2 = (const float*)d_in[6];
    float* out = (float*)d_out;

    cudaFuncSetAttribute(moe_gemm<1>, cudaFuncAttributeMaxDynamicSharedMemorySize, SMEM_BYTES);
    cudaFuncSetAttribute(moe_gemm<2>, cudaFuncAttributeMaxDynamicSharedMemorySize, SMEM_BYTES);

    // main output accumulated via atomics -> zero it (logits tail written directly)
    cudaMemsetAsync(out, 0, (size_t)NTOK*DDIM*sizeof(float));
    init_kernel<<<1, 32>>>();

    int write_logits = (out_size >= NTOK*DDIM + NTOK*EEXP) ? 1 : 0;
    router_kernel<<<NTOK/8, 256>>>(x, Wg, bg, out + (size_t)NTOK*DDIM, write_logits);
    offsets_kernel<<<1, 1>>>();

    moe_gemm<1><<<dim3(HDIM/BN, NTOK/BM, EEXP), 256, SMEM_BYTES>>>(x, w1, b1, out);
    moe_gemm<2><<<dim3(DDIM/BN, NTOK/BM, EEXP), 256, SMEM_BYTES>>>(x, w2, b2, out);
}

// round 3
// speedup vs baseline: 2.8299x; 2.8299x over previous
#include <cuda_runtime.h>
#include <cuda_fp16.h>
#include <cstdint>
#include <mma.h>
using namespace nvcuda;

#define NTOK 4096
#define DDIM 1024
#define EEXP 8
#define HDIM 4096
#define NPAIR (NTOK*2)

#define BM 128
#define BN 128
#define BK 32
#define LDA 40            // halves (80B row stride, 16B-multiple)
#define LDB 136           // halves (272B row stride, 16B-multiple)
#define ASTAGE (BM*LDA)   // 5120 halves = 10240 B
#define BSTAGE (BK*LDB)   // 4352 halves = 8704 B
#define STAGE_H (ASTAGE + BSTAGE)
#define SMEM_BYTES (2*STAGE_H*2)   // 37888 B
#define LDC 132

// ---------------- device scratch (no runtime allocation allowed) ----------------
__device__ __half g_xa [(size_t)NPAIR*DDIM];       // gathered tokens, fp16
__device__ __half g_h  [(size_t)NPAIR*HDIM];       // hidden activations, fp16
__device__ __half g_w1h[(size_t)EEXP*DDIM*HDIM];   // w1 fp16 [e][d][h]
__device__ __half g_w2h[(size_t)EEXP*HDIM*DDIM];   // w2 fp16 [e][h][d]
__device__ int    g_counts[EEXP];
__device__ int    g_offsets[EEXP];
__device__ int    g_tok[EEXP*NTOK];
__device__ float  g_wt [EEXP*NTOK];
__device__ int    g_ftok[NPAIR];
__device__ float  g_fwt [NPAIR];

__device__ __forceinline__ void cpa16(void* dst, const void* src){
    uint32_t d = (uint32_t)__cvta_generic_to_shared(dst);
    asm volatile("cp.async.cg.shared.global [%0], [%1], 16;\n" :: "r"(d), "l"(src));
}
__device__ __forceinline__ void cp_commit(){ asm volatile("cp.async.commit_group;\n"); }
template<int N> __device__ __forceinline__ void cp_wait(){
    asm volatile("cp.async.wait_group %0;\n" :: "n"(N));
}

__device__ __forceinline__ float gelu_tanh(float v){
    const float c = 0.7978845608028654f;
    float t = tanhf(c*(v + 0.044715f*v*v*v));
    return 0.5f*v*(1.0f+t);
}

// ---------------- routing ----------------
__global__ void init_kernel(){
    int t = threadIdx.x;
    if (t < EEXP) g_counts[t] = 0;
}

__global__ void router_kernel(const float* __restrict__ x, const float* __restrict__ Wg,
                              const float* __restrict__ bg, float* __restrict__ logits_out,
                              int write_logits){
    int warp = threadIdx.x >> 5;
    int lane = threadIdx.x & 31;
    int n = blockIdx.x * 8 + warp;
    if (n >= NTOK) return;
    const float* xr = x + (size_t)n * DDIM;
    float l[EEXP];
    #pragma unroll
    for (int e = 0; e < EEXP; e++) l[e] = 0.f;
    for (int d = lane; d < DDIM; d += 32){
        float xv = xr[d];
        const float4* wp = (const float4*)(Wg + (size_t)d*EEXP);
        float4 wa = wp[0], wb = wp[1];
        l[0] += xv*wa.x; l[1] += xv*wa.y; l[2] += xv*wa.z; l[3] += xv*wa.w;
        l[4] += xv*wb.x; l[5] += xv*wb.y; l[6] += xv*wb.z; l[7] += xv*wb.w;
    }
    #pragma unroll
    for (int off = 16; off > 0; off >>= 1){
        #pragma unroll
        for (int e = 0; e < EEXP; e++)
            l[e] += __shfl_xor_sync(0xffffffff, l[e], off);
    }
    if (lane == 0){
        #pragma unroll
        for (int e = 0; e < EEXP; e++) l[e] += bg[e];
        if (write_logits){
            #pragma unroll
            for (int e = 0; e < EEXP; e++) logits_out[(size_t)n*EEXP + e] = l[e];
        }
        int e0 = 0;
        #pragma unroll
        for (int e = 1; e < EEXP; e++) if (l[e] > l[e0]) e0 = e;
        int e1 = (e0 == 0) ? 1 : 0;
        #pragma unroll
        for (int e = 0; e < EEXP; e++) if (e != e0 && l[e] > l[e1]) e1 = e;
        float a = l[e0], b = l[e1];
        float ex = expf(b - a);
        float s  = 1.0f / (1.0f + ex);
        float w0 = s, w1 = ex * s;
        int p0 = atomicAdd(&g_counts[e0], 1);
        g_tok[e0*NTOK + p0] = n; g_wt[e0*NTOK + p0] = w0;
        int p1 = atomicAdd(&g_counts[e1], 1);
        g_tok[e1*NTOK + p1] = n; g_wt[e1*NTOK + p1] = w1;
    }
}

__global__ void offsets_kernel(){
    if (threadIdx.x == 0){
        int s = 0;
        #pragma unroll
        for (int e = 0; e < EEXP; e++){ g_offsets[e] = s; s += g_counts[e]; }
    }
}

// ---------------- prep: fp32 -> fp16 weight convert (elementwise) ----------------
__global__ void conv_f2h(const float* __restrict__ in, __half* __restrict__ out, size_t n){
    size_t i = ((size_t)blockIdx.x * blockDim.x + threadIdx.x) * 8;
    if (i >= n) return;
    float4 v0 = *(const float4*)(in + i);
    float4 v1 = *(const float4*)(in + i + 4);
    __half2 h0 = __floats2half2_rn(v0.x, v0.y);
    __half2 h1 = __floats2half2_rn(v0.z, v0.w);
    __half2 h2 = __floats2half2_rn(v1.x, v1.y);
    __half2 h3 = __floats2half2_rn(v1.z, v1.w);
    uint4 pk = make_uint4(*(uint32_t*)&h0, *(uint32_t*)&h1, *(uint32_t*)&h2, *(uint32_t*)&h3);
    *(uint4*)(out + i) = pk;
}

// ---------------- prep: token gather + fp16 convert + flat pair lists ----------------
__global__ void gather_kernel(const float* __restrict__ x){
    int p = blockIdx.x;
    int e = 0;
    #pragma unroll
    for (int k = 1; k < EEXP; k++) if (p >= g_offsets[k]) e = k;
    int i = p - g_offsets[e];
    int tok = g_tok[e*NTOK + i];
    float wt = g_wt[e*NTOK + i];
    if (threadIdx.x == 0){ g_ftok[p] = tok; g_fwt[p] = wt; }
    const float4* src = (const float4*)(x + (size_t)tok*DDIM);
    __half2* dst = (__half2*)(g_xa + (size_t)p*DDIM);
    for (int j = threadIdx.x; j < DDIM/4; j += blockDim.x){
        float4 v = src[j];
        dst[2*j]     = __floats2half2_rn(v.x, v.y);
        dst[2*j + 1] = __floats2half2_rn(v.z, v.w);
    }
}

// ---------------- fp16 wmma GEMM ----------------
// MODE 1: g_h = gelu(g_xa @ w1h[e] + b1[e])   A=[pair,1024], B=[1024,4096] row-major
// MODE 2: out[tok] += wt*(g_h @ w2h[e] + b2[e])
template<int KDIM, int NDIM, int MODE>
__global__ void __launch_bounds__(256, 2)
moe_gemm(const __half* __restrict__ Amat, const __half* __restrict__ Bw,
         const float* __restrict__ bias, float* __restrict__ out){
    const int e = blockIdx.z;
    const int count = g_counts[e];
    const int mBase = blockIdx.y * BM;
    if (mBase >= count) return;
    const int off = g_offsets[e];
    const int n0 = blockIdx.x * BN;
    const int tid = threadIdx.x;

    extern __shared__ char smem_raw[];
    __half* Ab[2] = { (__half*)smem_raw, (__half*)smem_raw + STAGE_H };
    __half* Bb[2] = { (__half*)smem_raw + ASTAGE, (__half*)smem_raw + STAGE_H + ASTAGE };

    // A: 512 chunks/stage (128 rows x 4 x 16B). Thread covers 2 chunks.
    const __half* asrc[2];
    int adoff[2];
    #pragma unroll
    for (int v = 0; v < 2; v++){
        int i = tid + v*256;
        int row = i >> 2, ch = i & 3;
        int m = mBase + row; if (m > count - 1) m = count - 1;
        asrc[v] = Amat + (size_t)(off + m)*KDIM + ch*8;
        adoff[v] = row*LDA + ch*8;
    }
    // B: 512 chunks/stage (32 rows x 16 x 16B). Thread covers 2 chunks.
    const __half* bsrc[2];
    int bdoff[2];
    const __half* Wb = Bw + (size_t)e*KDIM*NDIM + n0;
    #pragma unroll
    for (int v = 0; v < 2; v++){
        int i = tid + v*256;
        int row = i >> 4, ch = i & 15;
        bsrc[v] = Wb + (size_t)row*NDIM + ch*8;
        bdoff[v] = row*LDB + ch*8;
    }

    constexpr int KSTEPS = KDIM / BK;
    // prologue
    #pragma unroll
    for (int v = 0; v < 2; v++) cpa16(Ab[0] + adoff[v], asrc[v]);
    #pragma unroll
    for (int v = 0; v < 2; v++) cpa16(Bb[0] + bdoff[v], bsrc[v]);
    cp_commit();

    const int warpId = tid >> 5;
    const int wr = warpId & 3;   // 4 warp-rows x 32
    const int wc = warpId >> 2;  // 2 warp-cols x 64

    using FragA = wmma::fragment<wmma::matrix_a, 16,16,16, __half, wmma::row_major>;
    using FragB = wmma::fragment<wmma::matrix_b, 16,16,16, __half, wmma::row_major>;
    using FragC = wmma::fragment<wmma::accumulator, 16,16,16, float>;
    FragC acc[2][4];
    #pragma unroll
    for (int i = 0; i < 2; i++)
        #pragma unroll
        for (int j = 0; j < 4; j++) wmma::fill_fragment(acc[i][j], 0.0f);

    #pragma unroll 1
    for (int kt = 0; kt < KSTEPS; kt++){
        int cur = kt & 1;
        if (kt + 1 < KSTEPS){
            int nxt = cur ^ 1;
            size_t ka = (size_t)(kt+1) * BK;
            #pragma unroll
            for (int v = 0; v < 2; v++) cpa16(Ab[nxt] + adoff[v], asrc[v] + ka);
            #pragma unroll
            for (int v = 0; v < 2; v++) cpa16(Bb[nxt] + bdoff[v], bsrc[v] + ka*NDIM);
            cp_commit();
            cp_wait<1>();
        } else {
            cp_wait<0>();
        }
        __syncthreads();
        const __half* As = Ab[cur];
        const __half* Bs = Bb[cur];
        #pragma unroll
        for (int kk = 0; kk < BK; kk += 16){
            FragA a[2];
            #pragma unroll
            for (int i = 0; i < 2; i++)
                wmma::load_matrix_sync(a[i], As + (wr*32 + i*16)*LDA + kk, LDA);
            #pragma unroll
            for (int j = 0; j < 4; j++){
                FragB b;
                wmma::load_matrix_sync(b, Bs + kk*LDB + wc*64 + j*16, LDB);
                #pragma unroll
                for (int i = 0; i < 2; i++)
                    wmma::mma_sync(acc[i][j], a[i], b, acc[i][j]);
            }
        }
        __syncthreads();
    }

    // ---- epilogue in two 64-row halves (C staging fits 37KB smem) ----
    float* Cs = (float*)smem_raw;   // 64*132 floats = 33792 B
    const float* be = bias + (size_t)e*NDIM + n0;
    #pragma unroll 1
    for (int hf = 0; hf < 2; hf++){
        if ((wr >> 1) == hf){
            #pragma unroll
            for (int i = 0; i < 2; i++)
                #pragma unroll
                for (int j = 0; j < 4; j++)
                    wmma::store_matrix_sync(Cs + ((wr&1)*32 + i*16)*LDC + wc*64 + j*16,
                                            acc[i][j], LDC, wmma::mem_row_major);
        }
        __syncthreads();
        // 64 rows x 128 cols = 2048 float4-quads; 256 threads x 8 iters
        #pragma unroll 1
        for (int it = 0; it < 8; it++){
            int idx4 = tid + it*256;
            int row = idx4 >> 5;
            int c4  = (idx4 & 31) * 4;
            int gr = mBase + hf*64 + row;
            if (gr < count){
                float4 v  = *(const float4*)(Cs + row*LDC + c4);
                float4 bb = *(const float4*)(be + c4);
                if (MODE == 1){
                    float o0 = gelu_tanh(v.x + bb.x);
                    float o1 = gelu_tanh(v.y + bb.y);
                    float o2 = gelu_tanh(v.z + bb.z);
                    float o3 = gelu_tanh(v.w + bb.w);
                    __half2 h0 = __floats2half2_rn(o0, o1);
                    __half2 h1 = __floats2half2_rn(o2, o3);
                    uint2 pk = make_uint2(*(uint32_t*)&h0, *(uint32_t*)&h1);
                    *(uint2*)(g_h + (size_t)(off+gr)*HDIM + n0 + c4) = pk;
                } else {
                    int tok = g_ftok[off+gr];
                    float wgt = g_fwt[off+gr];
                    float* op = out + (size_t)tok*DDIM + n0 + c4;
                    atomicAdd(op + 0, wgt*(v.x + bb.x));
                    atomicAdd(op + 1, wgt*(v.y + bb.y));
                    atomicAdd(op + 2, wgt*(v.z + bb.z));
                    atomicAdd(op + 3, wgt*(v.w + bb.w));
                }
            }
        }
        __syncthreads();
    }
}

// ---------------- launch ----------------
extern "C" void kernel_launch(void* const* d_in, const int* in_sizes, int n_in,
                              void* d_out, int out_size){
    const float* x  = (const float*)d_in[0];
    const float* Wg = (const float*)d_in[1];
    const float* bg = (const float*)d_in[2];
    const float* w1 = (const float*)d_in[3];
    const float* b1 = (const float*)d_in[4];
    const float* w2 = (const float*)d_in[5];
    const float* b2 = (const float*)d_in[6];
    float* out = (float*)d_out;

    __half* w1h; cudaGetSymbolAddress((void**)&w1h, g_w1h);
    __half* w2h; cudaGetSymbolAddress((void**)&w2h, g_w2h);
    __half* xa;  cudaGetSymbolAddress((void**)&xa,  g_xa);
    __half* hbuf;cudaGetSymbolAddress((void**)&hbuf,g_h);

    cudaMemsetAsync(out, 0, (size_t)NTOK*DDIM*sizeof(float));
    init_kernel<<<1, 32>>>();

    int write_logits = (out_size >= NTOK*DDIM + NTOK*EEXP) ? 1 : 0;
    router_kernel<<<NTOK/8, 256>>>(x, Wg, bg, out + (size_t)NTOK*DDIM, write_logits);
    offsets_kernel<<<1, 1>>>();

    const size_t WN = (size_t)EEXP*DDIM*HDIM;
    conv_f2h<<<(int)(WN/8/256), 256>>>(w1, w1h, WN);
    conv_f2h<<<(int)(WN/8/256), 256>>>(w2, w2h, WN);
    gather_kernel<<<NPAIR, 128>>>(x);

    moe_gemm<DDIM, HDIM, 1><<<dim3(HDIM/BN, NTOK/BM, EEXP), 256, SMEM_BYTES>>>(
        xa, w1h, b1, out);
    moe_gemm<HDIM, DDIM, 2><<<dim3(DDIM/BN, NTOK/BM, EEXP), 256, SMEM_BYTES>>>(
        hbuf, w2h, b2, out);
}

// round 4
// speedup vs baseline: 3.2370x; 1.1439x over previous
#include <cuda_runtime.h>
#include <cuda_fp16.h>
#include <cstdint>
#include <mma.h>
using namespace nvcuda;

#define NTOK 4096
#define DDIM 1024
#define EEXP 8
#define HDIM 4096
#define NPAIR (NTOK*2)

#define BM 128
#define BN 256
#define BK 64
#define LDA 72            // halves (144B row stride)
#define LDB 264           // halves (528B row stride)
#define ASTAGE (BM*LDA)   // 9216 halves
#define BSTAGE (BK*LDB)   // 16896 halves
#define STAGE_H (ASTAGE + BSTAGE)          // 26112 halves = 52224 B
#define NSTAGE 3
#define SMEM_BYTES (NSTAGE*STAGE_H*2)      // 156672 B
#define LDC 264

// ---------------- device scratch ----------------
__device__ __half g_xa [(size_t)NPAIR*DDIM];
__device__ __half g_h  [(size_t)NPAIR*HDIM];
__device__ __half g_w1h[(size_t)EEXP*DDIM*HDIM];
__device__ __half g_w2h[(size_t)EEXP*HDIM*DDIM];
__device__ int    g_counts[EEXP];
__device__ int    g_offsets[EEXP];
__device__ int    g_tok[EEXP*NTOK];
__device__ float  g_wt [EEXP*NTOK];
__device__ int    g_ftok[NPAIR];
__device__ float  g_fwt [NPAIR];

__device__ __forceinline__ void cpa16(void* dst, const void* src){
    uint32_t d = (uint32_t)__cvta_generic_to_shared(dst);
    asm volatile("cp.async.cg.shared.global [%0], [%1], 16;\n" :: "r"(d), "l"(src));
}
__device__ __forceinline__ void cp_commit(){ asm volatile("cp.async.commit_group;\n"); }
template<int N> __device__ __forceinline__ void cp_wait(){
    asm volatile("cp.async.wait_group %0;\n" :: "n"(N));
}

__device__ __forceinline__ float gelu_tanh(float v){
    const float c = 0.7978845608028654f;
    float t = tanhf(c*(v + 0.044715f*v*v*v));
    return 0.5f*v*(1.0f+t);
}

// ---------------- routing ----------------
__global__ void init_kernel(){
    int t = threadIdx.x;
    if (t < EEXP) g_counts[t] = 0;
}

__global__ void router_kernel(const float* __restrict__ x, const float* __restrict__ Wg,
                              const float* __restrict__ bg, float* __restrict__ logits_out,
                              int write_logits){
    int warp = threadIdx.x >> 5;
    int lane = threadIdx.x & 31;
    int n = blockIdx.x * 8 + warp;
    if (n >= NTOK) return;
    const float* xr = x + (size_t)n * DDIM;
    float l[EEXP];
    #pragma unroll
    for (int e = 0; e < EEXP; e++) l[e] = 0.f;
    for (int d = lane; d < DDIM; d += 32){
        float xv = xr[d];
        const float4* wp = (const float4*)(Wg + (size_t)d*EEXP);
        float4 wa = wp[0], wb = wp[1];
        l[0] += xv*wa.x; l[1] += xv*wa.y; l[2] += xv*wa.z; l[3] += xv*wa.w;
        l[4] += xv*wb.x; l[5] += xv*wb.y; l[6] += xv*wb.z; l[7] += xv*wb.w;
    }
    #pragma unroll
    for (int off = 16; off > 0; off >>= 1){
        #pragma unroll
        for (int e = 0; e < EEXP; e++)
            l[e] += __shfl_xor_sync(0xffffffff, l[e], off);
    }
    if (lane == 0){
        #pragma unroll
        for (int e = 0; e < EEXP; e++) l[e] += bg[e];
        if (write_logits){
            #pragma unroll
            for (int e = 0; e < EEXP; e++) logits_out[(size_t)n*EEXP + e] = l[e];
        }
        int e0 = 0;
        #pragma unroll
        for (int e = 1; e < EEXP; e++) if (l[e] > l[e0]) e0 = e;
        int e1 = (e0 == 0) ? 1 : 0;
        #pragma unroll
        for (int e = 0; e < EEXP; e++) if (e != e0 && l[e] > l[e1]) e1 = e;
        float a = l[e0], b = l[e1];
        float ex = expf(b - a);
        float s  = 1.0f / (1.0f + ex);
        float w0 = s, w1 = ex * s;
        int p0 = atomicAdd(&g_counts[e0], 1);
        g_tok[e0*NTOK + p0] = n; g_wt[e0*NTOK + p0] = w0;
        int p1 = atomicAdd(&g_counts[e1], 1);
        g_tok[e1*NTOK + p1] = n; g_wt[e1*NTOK + p1] = w1;
    }
}

__global__ void offsets_kernel(){
    if (threadIdx.x == 0){
        int s = 0;
        #pragma unroll
        for (int e = 0; e < EEXP; e++){ g_offsets[e] = s; s += g_counts[e]; }
    }
}

// ---------------- prep ----------------
__global__ void conv_f2h(const float* __restrict__ in, __half* __restrict__ out, size_t n){
    size_t i = ((size_t)blockIdx.x * blockDim.x + threadIdx.x) * 8;
    if (i >= n) return;
    float4 v0 = *(const float4*)(in + i);
    float4 v1 = *(const float4*)(in + i + 4);
    __half2 h0 = __floats2half2_rn(v0.x, v0.y);
    __half2 h1 = __floats2half2_rn(v0.z, v0.w);
    __half2 h2 = __floats2half2_rn(v1.x, v1.y);
    __half2 h3 = __floats2half2_rn(v1.z, v1.w);
    uint4 pk = make_uint4(*(uint32_t*)&h0, *(uint32_t*)&h1, *(uint32_t*)&h2, *(uint32_t*)&h3);
    *(uint4*)(out + i) = pk;
}

__global__ void gather_kernel(const float* __restrict__ x){
    int p = blockIdx.x;
    int e = 0;
    #pragma unroll
    for (int k = 1; k < EEXP; k++) if (p >= g_offsets[k]) e = k;
    int i = p - g_offsets[e];
    int tok = g_tok[e*NTOK + i];
    float wt = g_wt[e*NTOK + i];
    if (threadIdx.x == 0){ g_ftok[p] = tok; g_fwt[p] = wt; }
    const float4* src = (const float4*)(x + (size_t)tok*DDIM);
    __half2* dst = (__half2*)(g_xa + (size_t)p*DDIM);
    for (int j = threadIdx.x; j < DDIM/4; j += blockDim.x){
        float4 v = src[j];
        dst[2*j]     = __floats2half2_rn(v.x, v.y);
        dst[2*j + 1] = __floats2half2_rn(v.z, v.w);
    }
}

// ---------------- fp16 wmma GEMM: CTA 128x256, warp tile 64x64, 3-stage ----------------
template<int KDIM, int NDIM, int MODE>
__global__ void __launch_bounds__(256, 1)
moe_gemm(const __half* __restrict__ Amat, const __half* __restrict__ Bw,
         const float* __restrict__ bias, float* __restrict__ out){
    const int e = blockIdx.z;
    const int count = g_counts[e];
    const int mBase = blockIdx.y * BM;
    if (mBase >= count) return;
    const int off = g_offsets[e];
    const int n0 = blockIdx.x * BN;
    const int tid = threadIdx.x;

    extern __shared__ char smem_raw[];
    __half* stg[NSTAGE];
    #pragma unroll
    for (int s = 0; s < NSTAGE; s++) stg[s] = (__half*)smem_raw + s*STAGE_H;

    // A: 128 rows x 64 halves = 1024 x 16B chunks; 4 per thread
    const __half* asrc[4];
    int adoff[4];
    #pragma unroll
    for (int v = 0; v < 4; v++){
        int i = tid + v*256;
        int row = i >> 3, ch = i & 7;
        int m = mBase + row; if (m > count - 1) m = count - 1;
        asrc[v] = Amat + (size_t)(off + m)*KDIM + ch*8;
        adoff[v] = row*LDA + ch*8;
    }
    // B: 64 rows x 256 halves = 2048 x 16B chunks; 8 per thread
    const __half* bsrc[8];
    int bdoff[8];
    const __half* Wb = Bw + (size_t)e*KDIM*NDIM + n0;
    #pragma unroll
    for (int v = 0; v < 8; v++){
        int i = tid + v*256;
        int row = i >> 5, ch = i & 31;
        bsrc[v] = Wb + (size_t)row*NDIM + ch*8;
        bdoff[v] = row*LDB + ch*8;
    }

    constexpr int KSTEPS = KDIM / BK;

    auto issue_stage = [&](int s){
        __half* Ab = stg[s % NSTAGE];
        __half* Bb = Ab + ASTAGE;
        size_t ka = (size_t)s * BK;
        #pragma unroll
        for (int v = 0; v < 4; v++) cpa16(Ab + adoff[v], asrc[v] + ka);
        #pragma unroll
        for (int v = 0; v < 8; v++) cpa16(Bb + bdoff[v], bsrc[v] + ka*NDIM);
        cp_commit();
    };

    issue_stage(0);
    issue_stage(1);

    const int warpId = tid >> 5;
    const int wr = warpId & 1;   // 2 M-warps x 64
    const int wc = warpId >> 1;  // 4 N-warps x 64

    using FragA = wmma::fragment<wmma::matrix_a, 16,16,16, __half, wmma::row_major>;
    using FragB = wmma::fragment<wmma::matrix_b, 16,16,16, __half, wmma::row_major>;
    using FragC = wmma::fragment<wmma::accumulator, 16,16,16, float>;
    FragC acc[4][4];
    #pragma unroll
    for (int i = 0; i < 4; i++)
        #pragma unroll
        for (int j = 0; j < 4; j++) wmma::fill_fragment(acc[i][j], 0.0f);

    #pragma unroll 1
    for (int kt = 0; kt < KSTEPS; kt++){
        cp_wait<1>();
        __syncthreads();           // stage kt ready; all warps done with kt-1's buffer
        if (kt + 2 < KSTEPS) issue_stage(kt + 2);

        const __half* As = stg[kt % NSTAGE];
        const __half* Bs = As + ASTAGE;
        #pragma unroll
        for (int kk = 0; kk < BK; kk += 16){
            FragA a[4];
            #pragma unroll
            for (int i = 0; i < 4; i++)
                wmma::load_matrix_sync(a[i], As + (wr*64 + i*16)*LDA + kk, LDA);
            #pragma unroll
            for (int j = 0; j < 4; j++){
                FragB b;
                wmma::load_matrix_sync(b, Bs + kk*LDB + wc*64 + j*16, LDB);
                #pragma unroll
                for (int i = 0; i < 4; i++)
                    wmma::mma_sync(acc[i][j], a[i], b, acc[i][j]);
            }
        }
    }
    __syncthreads();

    // ---- epilogue: two 64-row halves (Cs = 64 x 264 floats = 67.6KB, fits smem) ----
    float* Cs = (float*)smem_raw;
    const float* be = bias + (size_t)e*NDIM + n0;
    #pragma unroll 1
    for (int hf = 0; hf < 2; hf++){
        if (wr == hf){
            #pragma unroll
            for (int i = 0; i < 4; i++)
                #pragma unroll
                for (int j = 0; j < 4; j++)
                    wmma::store_matrix_sync(Cs + (i*16)*LDC + wc*64 + j*16,
                                            acc[i][j], LDC, wmma::mem_row_major);
        }
        __syncthreads();
        // 64 rows x 256 cols = 4096 float4s; 256 threads x 16 iters
        #pragma unroll 1
        for (int it = 0; it < 16; it++){
            int idx4 = tid + it*256;
            int row = idx4 >> 6;
            int c4  = (idx4 & 63) * 4;
            int gr = mBase + hf*64 + row;
            if (gr < count){
                float4 v  = *(const float4*)(Cs + row*LDC + c4);
                float4 bb = *(const float4*)(be + c4);
                if (MODE == 1){
                    float o0 = gelu_tanh(v.x + bb.x);
                    float o1 = gelu_tanh(v.y + bb.y);
                    float o2 = gelu_tanh(v.z + bb.z);
                    float o3 = gelu_tanh(v.w + bb.w);
                    __half2 h0 = __floats2half2_rn(o0, o1);
                    __half2 h1 = __floats2half2_rn(o2, o3);
                    uint2 pk = make_uint2(*(uint32_t*)&h0, *(uint32_t*)&h1);
                    *(uint2*)(g_h + (size_t)(off+gr)*HDIM + n0 + c4) = pk;
                } else {
                    int tok = g_ftok[off+gr];
                    float wgt = g_fwt[off+gr];
                    float* op = out + (size_t)tok*DDIM + n0 + c4;
                    atomicAdd(op + 0, wgt*(v.x + bb.x));
                    atomicAdd(op + 1, wgt*(v.y + bb.y));
                    atomicAdd(op + 2, wgt*(v.z + bb.z));
                    atomicAdd(op + 3, wgt*(v.w + bb.w));
                }
            }
        }
        __syncthreads();
    }
}

// ---------------- launch ----------------
extern "C" void kernel_launch(void* const* d_in, const int* in_sizes, int n_in,
                              void* d_out, int out_size){
    const float* x  = (const float*)d_in[0];
    const float* Wg = (const float*)d_in[1];
    const float* bg = (const float*)d_in[2];
    const float* w1 = (const float*)d_in[3];
    const float* b1 = (const float*)d_in[4];
    const float* w2 = (const float*)d_in[5];
    const float* b2 = (const float*)d_in[6];
    float* out = (float*)d_out;

    cudaFuncSetAttribute(moe_gemm<DDIM, HDIM, 1>,
                         cudaFuncAttributeMaxDynamicSharedMemorySize, SMEM_BYTES);
    cudaFuncSetAttribute(moe_gemm<HDIM, DDIM, 2>,
                         cudaFuncAttributeMaxDynamicSharedMemorySize, SMEM_BYTES);

    __half* w1h; cudaGetSymbolAddress((void**)&w1h, g_w1h);
    __half* w2h; cudaGetSymbolAddress((void**)&w2h, g_w2h);
    __half* xa;  cudaGetSymbolAddress((void**)&xa,  g_xa);
    __half* hbuf;cudaGetSymbolAddress((void**)&hbuf,g_h);

    cudaMemsetAsync(out, 0, (size_t)NTOK*DDIM*sizeof(float));
    init_kernel<<<1, 32>>>();

    int write_logits = (out_size >= NTOK*DDIM + NTOK*EEXP) ? 1 : 0;
    router_kernel<<<NTOK/8, 256>>>(x, Wg, bg, out + (size_t)NTOK*DDIM, write_logits);
    offsets_kernel<<<1, 1>>>();

    const size_t WN = (size_t)EEXP*DDIM*HDIM;
    conv_f2h<<<(int)(WN/8/256), 256>>>(w1, w1h, WN);
    conv_f2h<<<(int)(WN/8/256), 256>>>(w2, w2h, WN);
    gather_kernel<<<NPAIR, 128>>>(x);

    moe_gemm<DDIM, HDIM, 1><<<dim3(HDIM/BN, NTOK/BM, EEXP), 256, SMEM_BYTES>>>(
        xa, w1h, b1, out);
    moe_gemm<HDIM, DDIM, 2><<<dim3(DDIM/BN, NTOK/BM, EEXP), 256, SMEM_BYTES>>>(
        hbuf, w2h, b2, out);
}

// round 5
// speedup vs baseline: 3.8796x; 1.1985x over previous
#include <cuda_runtime.h>
#include <cuda_fp16.h>
#include <cstdint>
#include <mma.h>
using namespace nvcuda;

#define NTOK 4096
#define DDIM 1024
#define EEXP 8
#define HDIM 4096
#define NPAIR (NTOK*2)

#define BM 128
#define BN 256
#define BK 64
#define LDA 72            // halves (144B row stride)
#define LDB 264           // halves (528B row stride)
#define ASTAGE (BM*LDA)   // 9216 halves
#define BSTAGE (BK*LDB)   // 16896 halves
#define STAGE_H (ASTAGE + BSTAGE)          // 26112 halves = 52224 B
#define NSTAGE 4
#define SMEM_BYTES (NSTAGE*STAGE_H*2)      // 208896 B
#define LDC 264

// ---------------- device scratch ----------------
__device__ __half g_xa [(size_t)NPAIR*DDIM];
__device__ __half g_h  [(size_t)NPAIR*HDIM];
__device__ __half g_w1h[(size_t)EEXP*DDIM*HDIM];
__device__ __half g_w2h[(size_t)EEXP*HDIM*DDIM];
__device__ int    g_counts[EEXP];
__device__ int    g_offsets[EEXP];
__device__ int    g_mbp[EEXP+1];           // M-block prefix over experts
__device__ int    g_tilec[2];              // tile-steal counters (GEMM1, GEMM2)
__device__ int    g_tok[EEXP*NTOK];
__device__ float  g_wt [EEXP*NTOK];
__device__ int    g_ftok[NPAIR];
__device__ float  g_fwt [NPAIR];

__device__ __forceinline__ void cpa16(void* dst, const void* src){
    uint32_t d = (uint32_t)__cvta_generic_to_shared(dst);
    asm volatile("cp.async.cg.shared.global [%0], [%1], 16;\n" :: "r"(d), "l"(src));
}
__device__ __forceinline__ void cp_commit(){ asm volatile("cp.async.commit_group;\n"); }
template<int N> __device__ __forceinline__ void cp_wait(){
    asm volatile("cp.async.wait_group %0;\n" :: "n"(N));
}

__device__ __forceinline__ float gelu_tanh(float v){
    const float c = 0.7978845608028654f;
    float t = tanhf(c*(v + 0.044715f*v*v*v));
    return 0.5f*v*(1.0f+t);
}

// ---------------- routing ----------------
__global__ void init_kernel(){
    int t = threadIdx.x;
    if (t < EEXP) g_counts[t] = 0;
    if (t < 2) g_tilec[t] = 0;
}

__global__ void router_kernel(const float* __restrict__ x, const float* __restrict__ Wg,
                              const float* __restrict__ bg, float* __restrict__ logits_out,
                              int write_logits){
    int warp = threadIdx.x >> 5;
    int lane = threadIdx.x & 31;
    int n = blockIdx.x * 8 + warp;
    if (n >= NTOK) return;
    const float* xr = x + (size_t)n * DDIM;
    float l[EEXP];
    #pragma unroll
    for (int e = 0; e < EEXP; e++) l[e] = 0.f;
    for (int d = lane; d < DDIM; d += 32){
        float xv = xr[d];
        const float4* wp = (const float4*)(Wg + (size_t)d*EEXP);
        float4 wa = wp[0], wb = wp[1];
        l[0] += xv*wa.x; l[1] += xv*wa.y; l[2] += xv*wa.z; l[3] += xv*wa.w;
        l[4] += xv*wb.x; l[5] += xv*wb.y; l[6] += xv*wb.z; l[7] += xv*wb.w;
    }
    #pragma unroll
    for (int off = 16; off > 0; off >>= 1){
        #pragma unroll
        for (int e = 0; e < EEXP; e++)
            l[e] += __shfl_xor_sync(0xffffffff, l[e], off);
    }
    if (lane == 0){
        #pragma unroll
        for (int e = 0; e < EEXP; e++) l[e] += bg[e];
        if (write_logits){
            #pragma unroll
            for (int e = 0; e < EEXP; e++) logits_out[(size_t)n*EEXP + e] = l[e];
        }
        int e0 = 0;
        #pragma unroll
        for (int e = 1; e < EEXP; e++) if (l[e] > l[e0]) e0 = e;
        int e1 = (e0 == 0) ? 1 : 0;
        #pragma unroll
        for (int e = 0; e < EEXP; e++) if (e != e0 && l[e] > l[e1]) e1 = e;
        float a = l[e0], b = l[e1];
        float ex = expf(b - a);
        float s  = 1.0f / (1.0f + ex);
        float w0 = s, w1 = ex * s;
        int p0 = atomicAdd(&g_counts[e0], 1);
        g_tok[e0*NTOK + p0] = n; g_wt[e0*NTOK + p0] = w0;
        int p1 = atomicAdd(&g_counts[e1], 1);
        g_tok[e1*NTOK + p1] = n; g_wt[e1*NTOK + p1] = w1;
    }
}

__global__ void offsets_kernel(){
    if (threadIdx.x == 0){
        int s = 0, mb = 0;
        g_mbp[0] = 0;
        #pragma unroll
        for (int e = 0; e < EEXP; e++){
            g_offsets[e] = s; s += g_counts[e];
            mb += (g_counts[e] + BM - 1) / BM;
            g_mbp[e+1] = mb;
        }
    }
}

// ---------------- prep ----------------
__global__ void conv_f2h(const float* __restrict__ in, __half* __restrict__ out, size_t n){
    size_t i = ((size_t)blockIdx.x * blockDim.x + threadIdx.x) * 8;
    if (i >= n) return;
    float4 v0 = *(const float4*)(in + i);
    float4 v1 = *(const float4*)(in + i + 4);
    __half2 h0 = __floats2half2_rn(v0.x, v0.y);
    __half2 h1 = __floats2half2_rn(v0.z, v0.w);
    __half2 h2 = __floats2half2_rn(v1.x, v1.y);
    __half2 h3 = __floats2half2_rn(v1.z, v1.w);
    uint4 pk = make_uint4(*(uint32_t*)&h0, *(uint32_t*)&h1, *(uint32_t*)&h2, *(uint32_t*)&h3);
    *(uint4*)(out + i) = pk;
}

__global__ void gather_kernel(const float* __restrict__ x){
    int p = blockIdx.x;
    int e = 0;
    #pragma unroll
    for (int k = 1; k < EEXP; k++) if (p >= g_offsets[k]) e = k;
    int i = p - g_offsets[e];
    int tok = g_tok[e*NTOK + i];
    float wt = g_wt[e*NTOK + i];
    if (threadIdx.x == 0){ g_ftok[p] = tok; g_fwt[p] = wt; }
    const float4* src = (const float4*)(x + (size_t)tok*DDIM);
    __half2* dst = (__half2*)(g_xa + (size_t)p*DDIM);
    for (int j = threadIdx.x; j < DDIM/4; j += blockDim.x){
        float4 v = src[j];
        dst[2*j]     = __floats2half2_rn(v.x, v.y);
        dst[2*j + 1] = __floats2half2_rn(v.z, v.w);
    }
}

// ---------------- persistent fp16 wmma GEMM: tile stealing, 4-stage pipeline ----------------
// Tile order M-fastest: nb = t / mbTotal, gmb = t % mbTotal  (concurrent CTAs share B panels)
template<int KDIM, int NDIM, int MODE>
__global__ void __launch_bounds__(256, 1)
moe_gemm(const __half* __restrict__ Amat, const __half* __restrict__ Bw,
         const float* __restrict__ bias, float* __restrict__ out){
    const int tid = threadIdx.x;
    const int warpId = tid >> 5;
    const int wr = warpId & 1;   // 2 M-warps x 64
    const int wc = warpId >> 1;  // 4 N-warps x 64
    constexpr int NB = NDIM / BN;
    constexpr int KSTEPS = KDIM / BK;

    extern __shared__ char smem_raw[];
    __shared__ int sTile;

    // expert prefix (static during this kernel)
    int mbp[EEXP+1];
    #pragma unroll
    for (int i = 0; i <= EEXP; i++) mbp[i] = g_mbp[i];
    const int mbTotal = mbp[EEXP];
    const int totalTiles = mbTotal * NB;

    using FragA = wmma::fragment<wmma::matrix_a, 16,16,16, __half, wmma::row_major>;
    using FragB = wmma::fragment<wmma::matrix_b, 16,16,16, __half, wmma::row_major>;
    using FragC = wmma::fragment<wmma::accumulator, 16,16,16, float>;

    while (true){
        if (tid == 0) sTile = atomicAdd(&g_tilec[MODE-1], 1);
        __syncthreads();
        const int t = sTile;
        __syncthreads();
        if (t >= totalTiles) break;

        const int nb = t / mbTotal;
        const int gmb = t - nb * mbTotal;
        int e = 0;
        #pragma unroll
        for (int k = 1; k < EEXP; k++) if (gmb >= mbp[k]) e = k;
        const int mb = gmb - mbp[e];
        const int count = g_counts[e];
        const int off = g_offsets[e];
        const int mBase = mb * BM;
        const int n0 = nb * BN;

        // per-tile load slots
        const __half* asrc[4];
        int adoff[4];
        #pragma unroll
        for (int v = 0; v < 4; v++){
            int i = tid + v*256;
            int row = i >> 3, ch = i & 7;
            int m = mBase + row; if (m > count - 1) m = count - 1;
            asrc[v] = Amat + (size_t)(off + m)*KDIM + ch*8;
            adoff[v] = row*LDA + ch*8;
        }
        const __half* bsrc[8];
        int bdoff[8];
        const __half* Wb = Bw + (size_t)e*KDIM*NDIM + n0;
        #pragma unroll
        for (int v = 0; v < 8; v++){
            int i = tid + v*256;
            int row = i >> 5, ch = i & 31;
            bsrc[v] = Wb + (size_t)row*NDIM + ch*8;
            bdoff[v] = row*LDB + ch*8;
        }

        auto issue_stage = [&](int s){
            if (s < KSTEPS){
                __half* Ab = (__half*)smem_raw + (s % NSTAGE)*STAGE_H;
                __half* Bb = Ab + ASTAGE;
                size_t ka = (size_t)s * BK;
                #pragma unroll
                for (int v = 0; v < 4; v++) cpa16(Ab + adoff[v], asrc[v] + ka);
                #pragma unroll
                for (int v = 0; v < 8; v++) cpa16(Bb + bdoff[v], bsrc[v] + ka*NDIM);
            }
            cp_commit();   // empty group past the end keeps wait-depth accounting constant
        };

        issue_stage(0); issue_stage(1); issue_stage(2);

        FragC acc[4][4];
        #pragma unroll
        for (int i = 0; i < 4; i++)
            #pragma unroll
            for (int j = 0; j < 4; j++) wmma::fill_fragment(acc[i][j], 0.0f);

        #pragma unroll 1
        for (int kt = 0; kt < KSTEPS; kt++){
            cp_wait<2>();
            __syncthreads();           // stage kt ready; all warps done with buffer (kt-1)
            issue_stage(kt + 3);

            const __half* As = (__half*)smem_raw + (kt % NSTAGE)*STAGE_H;
            const __half* Bs = As + ASTAGE;
            #pragma unroll
            for (int kk = 0; kk < BK; kk += 16){
                FragA a[4];
                #pragma unroll
                for (int i = 0; i < 4; i++)
                    wmma::load_matrix_sync(a[i], As + (wr*64 + i*16)*LDA + kk, LDA);
                #pragma unroll
                for (int j = 0; j < 4; j++){
                    FragB b;
                    wmma::load_matrix_sync(b, Bs + kk*LDB + wc*64 + j*16, LDB);
                    #pragma unroll
                    for (int i = 0; i < 4; i++)
                        wmma::mma_sync(acc[i][j], a[i], b, acc[i][j]);
                }
            }
        }
        cp_wait<0>();      // drain empty tail groups before next tile
        __syncthreads();

        // ---- epilogue: two 64-row halves staged in smem ----
        float* Cs = (float*)smem_raw;
        const float* be = bias + (size_t)e*NDIM + n0;
        #pragma unroll 1
        for (int hf = 0; hf < 2; hf++){
            if (wr == hf){
                #pragma unroll
                for (int i = 0; i < 4; i++)
                    #pragma unroll
                    for (int j = 0; j < 4; j++)
                        wmma::store_matrix_sync(Cs + (i*16)*LDC + wc*64 + j*16,
                                                acc[i][j], LDC, wmma::mem_row_major);
            }
            __syncthreads();
            #pragma unroll 1
            for (int it = 0; it < 16; it++){
                int idx4 = tid + it*256;
                int row = idx4 >> 6;
                int c4  = (idx4 & 63) * 4;
                int gr = mBase + hf*64 + row;
                if (gr < count){
                    float4 v  = *(const float4*)(Cs + row*LDC + c4);
                    float4 bb = *(const float4*)(be + c4);
                    if (MODE == 1){
                        float o0 = gelu_tanh(v.x + bb.x);
                        float o1 = gelu_tanh(v.y + bb.y);
                        float o2 = gelu_tanh(v.z + bb.z);
                        float o3 = gelu_tanh(v.w + bb.w);
                        __half2 h0 = __floats2half2_rn(o0, o1);
                        __half2 h1 = __floats2half2_rn(o2, o3);
                        uint2 pk = make_uint2(*(uint32_t*)&h0, *(uint32_t*)&h1);
                        *(uint2*)(g_h + (size_t)(off+gr)*HDIM + n0 + c4) = pk;
                    } else {
                        int tok = g_ftok[off+gr];
                        float wgt = g_fwt[off+gr];
                        float* op = out + (size_t)tok*DDIM + n0 + c4;
                        atomicAdd(op + 0, wgt*(v.x + bb.x));
                        atomicAdd(op + 1, wgt*(v.y + bb.y));
                        atomicAdd(op + 2, wgt*(v.z + bb.z));
                        atomicAdd(op + 3, wgt*(v.w + bb.w));
                    }
                }
            }
            __syncthreads();
        }
    }
}

// ---------------- launch ----------------
extern "C" void kernel_launch(void* const* d_in, const int* in_sizes, int n_in,
                              void* d_out, int out_size){
    const float* x  = (const float*)d_in[0];
    const float* Wg = (const float*)d_in[1];
    const float* bg = (const float*)d_in[2];
    const float* w1 = (const float*)d_in[3];
    const float* b1 = (const float*)d_in[4];
    const float* w2 = (const float*)d_in[5];
    const float* b2 = (const float*)d_in[6];
    float* out = (float*)d_out;

    cudaFuncSetAttribute(moe_gemm<DDIM, HDIM, 1>,
                         cudaFuncAttributeMaxDynamicSharedMemorySize, SMEM_BYTES);
    cudaFuncSetAttribute(moe_gemm<HDIM, DDIM, 2>,
                         cudaFuncAttributeMaxDynamicSharedMemorySize, SMEM_BYTES);

    int dev = 0, nsm = 148;
    cudaGetDevice(&dev);
    cudaDeviceGetAttribute(&nsm, cudaDevAttrMultiProcessorCount, dev);

    __half* w1h; cudaGetSymbolAddress((void**)&w1h, g_w1h);
    __half* w2h; cudaGetSymbolAddress((void**)&w2h, g_w2h);
    __half* xa;  cudaGetSymbolAddress((void**)&xa,  g_xa);
    __half* hbuf;cudaGetSymbolAddress((void**)&hbuf,g_h);

    cudaMemsetAsync(out, 0, (size_t)NTOK*DDIM*sizeof(float));
    init_kernel<<<1, 32>>>();

    int write_logits = (out_size >= NTOK*DDIM + NTOK*EEXP) ? 1 : 0;
    router_kernel<<<NTOK/8, 256>>>(x, Wg, bg, out + (size_t)NTOK*DDIM, write_logits);
    offsets_kernel<<<1, 1>>>();

    const size_t WN = (size_t)EEXP*DDIM*HDIM;
    conv_f2h<<<(int)(WN/8/256), 256>>>(w1, w1h, WN);
    conv_f2h<<<(int)(WN/8/256), 256>>>(w2, w2h, WN);
    gather_kernel<<<NPAIR, 128>>>(x);

    moe_gemm<DDIM, HDIM, 1><<<nsm, 256, SMEM_BYTES>>>(xa, w1h, b1, out);
    moe_gemm<HDIM, DDIM, 2><<<nsm, 256, SMEM_BYTES>>>(hbuf, w2h, b2, out);
}

// round 6
// speedup vs baseline: 3.9000x; 1.0052x over previous
#include <cuda_runtime.h>
#include <cuda_fp16.h>
#include <cstdint>
#include <mma.h>
using namespace nvcuda;

#define NTOK 4096
#define DDIM 1024
#define EEXP 8
#define HDIM 4096
#define NPAIR (NTOK*2)

#define BM 128
#define BN 256
#define BK 64
#define LDA 72            // halves (144B row stride)
#define LDB 264           // halves (528B row stride)
#define ASTAGE (BM*LDA)   // 9216 halves
#define BSTAGE (BK*LDB)   // 16896 halves
#define STAGE_H (ASTAGE + BSTAGE)          // 26112 halves = 52224 B
#define NSTAGE 4
#define SMEM_BYTES (NSTAGE*STAGE_H*2)      // 208896 B
#define LDC 264

// ---------------- device scratch ----------------
__device__ __half g_xa [(size_t)NPAIR*DDIM];
__device__ __half g_h  [(size_t)NPAIR*HDIM];
__device__ __half g_w1h[(size_t)EEXP*DDIM*HDIM];
__device__ __half g_w2h[(size_t)EEXP*HDIM*DDIM];
__device__ int    g_counts[EEXP];
__device__ int    g_offsets[EEXP];
__device__ int    g_mbp[EEXP+1];
__device__ int    g_tilec[2];
__device__ int    g_tok[EEXP*NTOK];
__device__ float  g_wt [EEXP*NTOK];
__device__ int    g_ftok[NPAIR];
__device__ float  g_fwt [NPAIR];

__device__ __forceinline__ void cpa16(void* dst, const void* src){
    uint32_t d = (uint32_t)__cvta_generic_to_shared(dst);
    asm volatile("cp.async.cg.shared.global [%0], [%1], 16;\n" :: "r"(d), "l"(src));
}
__device__ __forceinline__ void cp_commit(){ asm volatile("cp.async.commit_group;\n"); }
template<int N> __device__ __forceinline__ void cp_wait(){
    asm volatile("cp.async.wait_group %0;\n" :: "n"(N));
}

__device__ __forceinline__ float gelu_tanh(float v){
    const float c = 0.7978845608028654f;
    float t = tanhf(c*(v + 0.044715f*v*v*v));
    return 0.5f*v*(1.0f+t);
}

// ---------------- routing ----------------
__global__ void init_kernel(){
    int t = threadIdx.x;
    if (t < EEXP) g_counts[t] = 0;
    if (t < 2) g_tilec[t] = 0;
}

__global__ void router_kernel(const float* __restrict__ x, const float* __restrict__ Wg,
                              const float* __restrict__ bg, float* __restrict__ logits_out,
                              int write_logits){
    int warp = threadIdx.x >> 5;
    int lane = threadIdx.x & 31;
    int n = blockIdx.x * 8 + warp;
    if (n >= NTOK) return;
    const float* xr = x + (size_t)n * DDIM;
    float l[EEXP];
    #pragma unroll
    for (int e = 0; e < EEXP; e++) l[e] = 0.f;
    for (int d = lane; d < DDIM; d += 32){
        float xv = xr[d];
        const float4* wp = (const float4*)(Wg + (size_t)d*EEXP);
        float4 wa = wp[0], wb = wp[1];
        l[0] += xv*wa.x; l[1] += xv*wa.y; l[2] += xv*wa.z; l[3] += xv*wa.w;
        l[4] += xv*wb.x; l[5] += xv*wb.y; l[6] += xv*wb.z; l[7] += xv*wb.w;
    }
    #pragma unroll
    for (int off = 16; off > 0; off >>= 1){
        #pragma unroll
        for (int e = 0; e < EEXP; e++)
            l[e] += __shfl_xor_sync(0xffffffff, l[e], off);
    }
    if (lane == 0){
        #pragma unroll
        for (int e = 0; e < EEXP; e++) l[e] += bg[e];
        if (write_logits){
            #pragma unroll
            for (int e = 0; e < EEXP; e++) logits_out[(size_t)n*EEXP + e] = l[e];
        }
        int e0 = 0;
        #pragma unroll
        for (int e = 1; e < EEXP; e++) if (l[e] > l[e0]) e0 = e;
        int e1 = (e0 == 0) ? 1 : 0;
        #pragma unroll
        for (int e = 0; e < EEXP; e++) if (e != e0 && l[e] > l[e1]) e1 = e;
        float a = l[e0], b = l[e1];
        float ex = expf(b - a);
        float s  = 1.0f / (1.0f + ex);
        float w0 = s, w1 = ex * s;
        int p0 = atomicAdd(&g_counts[e0], 1);
        g_tok[e0*NTOK + p0] = n; g_wt[e0*NTOK + p0] = w0;
        int p1 = atomicAdd(&g_counts[e1], 1);
        g_tok[e1*NTOK + p1] = n; g_wt[e1*NTOK + p1] = w1;
    }
}

__global__ void offsets_kernel(){
    if (threadIdx.x == 0){
        int s = 0, mb = 0;
        g_mbp[0] = 0;
        #pragma unroll
        for (int e = 0; e < EEXP; e++){
            g_offsets[e] = s; s += g_counts[e];
            mb += (g_counts[e] + BM - 1) / BM;
            g_mbp[e+1] = mb;
        }
    }
}

// ---------------- prep ----------------
__global__ void conv_f2h(const float* __restrict__ in, __half* __restrict__ out, size_t n){
    size_t i = ((size_t)blockIdx.x * blockDim.x + threadIdx.x) * 8;
    if (i >= n) return;
    float4 v0 = *(const float4*)(in + i);
    float4 v1 = *(const float4*)(in + i + 4);
    __half2 h0 = __floats2half2_rn(v0.x, v0.y);
    __half2 h1 = __floats2half2_rn(v0.z, v0.w);
    __half2 h2 = __floats2half2_rn(v1.x, v1.y);
    __half2 h3 = __floats2half2_rn(v1.z, v1.w);
    uint4 pk = make_uint4(*(uint32_t*)&h0, *(uint32_t*)&h1, *(uint32_t*)&h2, *(uint32_t*)&h3);
    *(uint4*)(out + i) = pk;
}

__global__ void gather_kernel(const float* __restrict__ x){
    int p = blockIdx.x;
    int e = 0;
    #pragma unroll
    for (int k = 1; k < EEXP; k++) if (p >= g_offsets[k]) e = k;
    int i = p - g_offsets[e];
    int tok = g_tok[e*NTOK + i];
    float wt = g_wt[e*NTOK + i];
    if (threadIdx.x == 0){ g_ftok[p] = tok; g_fwt[p] = wt; }
    const float4* src = (const float4*)(x + (size_t)tok*DDIM);
    __half2* dst = (__half2*)(g_xa + (size_t)p*DDIM);
    for (int j = threadIdx.x; j < DDIM/4; j += blockDim.x){
        float4 v = src[j];
        dst[2*j]     = __floats2half2_rn(v.x, v.y);
        dst[2*j + 1] = __floats2half2_rn(v.z, v.w);
    }
}

// ---------------- persistent fp16 wmma GEMM: tile stealing, 4-stage pipeline ----------------
template<int KDIM, int NDIM, int MODE>
__global__ void __launch_bounds__(256, 1)
moe_gemm(const __half* __restrict__ Amat, const __half* __restrict__ Bw,
         const float* __restrict__ bias, float* __restrict__ out){
    const int tid = threadIdx.x;
    const int warpId = tid >> 5;
    const int wr = warpId & 1;   // 2 M-warps x 64
    const int wc = warpId >> 1;  // 4 N-warps x 64
    constexpr int NB = NDIM / BN;
    constexpr int KSTEPS = KDIM / BK;

    extern __shared__ char smem_raw[];
    __shared__ int sTile;

    int mbp[EEXP+1];
    #pragma unroll
    for (int i = 0; i <= EEXP; i++) mbp[i] = g_mbp[i];
    const int mbTotal = mbp[EEXP];
    const int totalTiles = mbTotal * NB;

    using FragA = wmma::fragment<wmma::matrix_a, 16,16,16, __half, wmma::row_major>;
    using FragB = wmma::fragment<wmma::matrix_b, 16,16,16, __half, wmma::row_major>;
    using FragC = wmma::fragment<wmma::accumulator, 16,16,16, float>;

    while (true){
        if (tid == 0) sTile = atomicAdd(&g_tilec[MODE-1], 1);
        __syncthreads();
        const int t = sTile;
        __syncthreads();
        if (t >= totalTiles) break;

        const int nb = t / mbTotal;
        const int gmb = t - nb * mbTotal;
        int e = 0;
        #pragma unroll
        for (int k = 1; k < EEXP; k++) if (gmb >= mbp[k]) e = k;
        const int mb = gmb - mbp[e];
        const int count = g_counts[e];
        const int off = g_offsets[e];
        const int mBase = mb * BM;
        const int n0 = nb * BN;

        const __half* asrc[4];
        int adoff[4];
        #pragma unroll
        for (int v = 0; v < 4; v++){
            int i = tid + v*256;
            int row = i >> 3, ch = i & 7;
            int m = mBase + row; if (m > count - 1) m = count - 1;
            asrc[v] = Amat + (size_t)(off + m)*KDIM + ch*8;
            adoff[v] = row*LDA + ch*8;
        }
        const __half* bsrc[8];
        int bdoff[8];
        const __half* Wb = Bw + (size_t)e*KDIM*NDIM + n0;
        #pragma unroll
        for (int v = 0; v < 8; v++){
            int i = tid + v*256;
            int row = i >> 5, ch = i & 31;
            bsrc[v] = Wb + (size_t)row*NDIM + ch*8;
            bdoff[v] = row*LDB + ch*8;
        }

        auto issue_stage = [&](int s){
            if (s < KSTEPS){
                __half* Ab = (__half*)smem_raw + (s % NSTAGE)*STAGE_H;
                __half* Bb = Ab + ASTAGE;
                size_t ka = (size_t)s * BK;
                #pragma unroll
                for (int v = 0; v < 4; v++) cpa16(Ab + adoff[v], asrc[v] + ka);
                #pragma unroll
                for (int v = 0; v < 8; v++) cpa16(Bb + bdoff[v], bsrc[v] + ka*NDIM);
            }
            cp_commit();
        };

        issue_stage(0); issue_stage(1); issue_stage(2);

        FragC acc[4][4];
        #pragma unroll
        for (int i = 0; i < 4; i++)
            #pragma unroll
            for (int j = 0; j < 4; j++) wmma::fill_fragment(acc[i][j], 0.0f);

        #pragma unroll 1
        for (int kt = 0; kt < KSTEPS; kt++){
            cp_wait<2>();
            __syncthreads();
            issue_stage(kt + 3);

            const __half* As = (__half*)smem_raw + (kt % NSTAGE)*STAGE_H;
            const __half* Bs = As + ASTAGE;
            #pragma unroll
            for (int kk = 0; kk < BK; kk += 16){
                FragA a[4];
                #pragma unroll
                for (int i = 0; i < 4; i++)
                    wmma::load_matrix_sync(a[i], As + (wr*64 + i*16)*LDA + kk, LDA);
                #pragma unroll
                for (int j = 0; j < 4; j++){
                    FragB b;
                    wmma::load_matrix_sync(b, Bs + kk*LDB + wc*64 + j*16, LDB);
                    #pragma unroll
                    for (int i = 0; i < 4; i++)
                        wmma::mma_sync(acc[i][j], a[i], b, acc[i][j]);
                }
            }
        }
        cp_wait<0>();
        __syncthreads();

        float* Cs = (float*)smem_raw;
        const float* be = bias + (size_t)e*NDIM + n0;
        #pragma unroll 1
        for (int hf = 0; hf < 2; hf++){
            if (wr == hf){
                #pragma unroll
                for (int i = 0; i < 4; i++)
                    #pragma unroll
                    for (int j = 0; j < 4; j++)
                        wmma::store_matrix_sync(Cs + (i*16)*LDC + wc*64 + j*16,
                                                acc[i][j], LDC, wmma::mem_row_major);
            }
            __syncthreads();
            #pragma unroll 1
            for (int it = 0; it < 16; it++){
                int idx4 = tid + it*256;
                int row = idx4 >> 6;
                int c4  = (idx4 & 63) * 4;
                int gr = mBase + hf*64 + row;
                if (gr < count){
                    float4 v  = *(const float4*)(Cs + row*LDC + c4);
                    float4 bb = *(const float4*)(be + c4);
                    if (MODE == 1){
                        float o0 = gelu_tanh(v.x + bb.x);
                        float o1 = gelu_tanh(v.y + bb.y);
                        float o2 = gelu_tanh(v.z + bb.z);
                        float o3 = gelu_tanh(v.w + bb.w);
                        __half2 h0 = __floats2half2_rn(o0, o1);
                        __half2 h1 = __floats2half2_rn(o2, o3);
                        uint2 pk = make_uint2(*(uint32_t*)&h0, *(uint32_t*)&h1);
                        *(uint2*)(g_h + (size_t)(off+gr)*HDIM + n0 + c4) = pk;
                    } else {
                        int tok = g_ftok[off+gr];
                        float wgt = g_fwt[off+gr];
                        float* op = out + (size_t)tok*DDIM + n0 + c4;
                        atomicAdd(op + 0, wgt*(v.x + bb.x));
                        atomicAdd(op + 1, wgt*(v.y + bb.y));
                        atomicAdd(op + 2, wgt*(v.z + bb.z));
                        atomicAdd(op + 3, wgt*(v.w + bb.w));
                    }
                }
            }
            __syncthreads();
        }
    }
}

// ---------------- launch: fork/join streams so weight conversion overlaps GEMM1 ----------------
extern "C" void kernel_launch(void* const* d_in, const int* in_sizes, int n_in,
                              void* d_out, int out_size){
    const float* x  = (const float*)d_in[0];
    const float* Wg = (const float*)d_in[1];
    const float* bg = (const float*)d_in[2];
    const float* w1 = (const float*)d_in[3];
    const float* b1 = (const float*)d_in[4];
    const float* w2 = (const float*)d_in[5];
    const float* b2 = (const float*)d_in[6];
    float* out = (float*)d_out;

    cudaFuncSetAttribute(moe_gemm<DDIM, HDIM, 1>,
                         cudaFuncAttributeMaxDynamicSharedMemorySize, SMEM_BYTES);
    cudaFuncSetAttribute(moe_gemm<HDIM, DDIM, 2>,
                         cudaFuncAttributeMaxDynamicSharedMemorySize, SMEM_BYTES);

    int dev = 0, nsm = 148;
    cudaGetDevice(&dev);
    cudaDeviceGetAttribute(&nsm, cudaDevAttrMultiProcessorCount, dev);

    __half* w1h; cudaGetSymbolAddress((void**)&w1h, g_w1h);
    __half* w2h; cudaGetSymbolAddress((void**)&w2h, g_w2h);
    __half* xa;  cudaGetSymbolAddress((void**)&xa,  g_xa);
    __half* hbuf;cudaGetSymbolAddress((void**)&hbuf,g_h);

    cudaStream_t s1;
    cudaStreamCreateWithFlags(&s1, cudaStreamNonBlocking);
    cudaEvent_t evStart, evW1, evW2;
    cudaEventCreateWithFlags(&evStart, cudaEventDisableTiming);
    cudaEventCreateWithFlags(&evW1,    cudaEventDisableTiming);
    cudaEventCreateWithFlags(&evW2,    cudaEventDisableTiming);

    const size_t WN = (size_t)EEXP*DDIM*HDIM;
    int write_logits = (out_size >= NTOK*DDIM + NTOK*EEXP) ? 1 : 0;

    // fork: weight conversions on s1 (independent of routing)
    cudaEventRecord(evStart, 0);
    cudaStreamWaitEvent(s1, evStart, 0);
    conv_f2h<<<(int)(WN/8/256), 256, 0, s1>>>(w1, w1h, WN);
    cudaEventRecord(evW1, s1);
    conv_f2h<<<(int)(WN/8/256), 256, 0, s1>>>(w2, w2h, WN);
    cudaEventRecord(evW2, s1);

    // routing chain on the capture stream
    cudaMemsetAsync(out, 0, (size_t)NTOK*DDIM*sizeof(float));
    init_kernel<<<1, 32>>>();
    router_kernel<<<NTOK/8, 256>>>(x, Wg, bg, out + (size_t)NTOK*DDIM, write_logits);
    offsets_kernel<<<1, 1>>>();
    gather_kernel<<<NPAIR, 128>>>(x);

    // GEMM1 needs gather (same stream) + conv_w1; conv_w2 overlaps GEMM1
    cudaStreamWaitEvent(0, evW1, 0);
    moe_gemm<DDIM, HDIM, 1><<<nsm, 256, SMEM_BYTES>>>(xa, w1h, b1, out);
    cudaStreamWaitEvent(0, evW2, 0);
    moe_gemm<HDIM, DDIM, 2><<<nsm, 256, SMEM_BYTES>>>(hbuf, w2h, b2, out);
}